// round 1
// baseline (speedup 1.0000x reference)
#include <cuda_runtime.h>
#include <cstdint>

// MultiVariatePoly: out[n] = sum_{i,j,k} W[i*100+j*10+k] * P_i(x[n,0]) * P_j(x[n,1]) * P_k(x[n,2]) + b
// DIM=3, ORDER=9 -> 10 polys per dim, 1000-term contraction per point.
// Strategy: 2 points per thread, all math in packed fp32 (fma.rn.f32x2),
// W pre-splatted to shared as float2{w,w}, read 2 splat-pairs per LDS.128.

#define NP1 10      // ORDER+1
#define NFEAT 1000  // NP1^3

typedef unsigned long long u64;

__device__ __forceinline__ u64 f2_pack(float lo, float hi) {
    u64 d; asm("mov.b64 %0, {%1, %2};" : "=l"(d) : "f"(lo), "f"(hi)); return d;
}
__device__ __forceinline__ u64 f2_splat(float s) {
    u64 d; asm("mov.b64 %0, {%1, %1};" : "=l"(d) : "f"(s)); return d;
}
__device__ __forceinline__ void f2_unpack(u64 v, float& lo, float& hi) {
    asm("mov.b64 {%0, %1}, %2;" : "=f"(lo), "=f"(hi) : "l"(v));
}
__device__ __forceinline__ u64 f2_fma(u64 a, u64 b, u64 c) {
    u64 d; asm("fma.rn.f32x2 %0, %1, %2, %3;" : "=l"(d) : "l"(a), "l"(b), "l"(c)); return d;
}
__device__ __forceinline__ u64 f2_mul(u64 a, u64 b) {
    u64 d; asm("mul.rn.f32x2 %0, %1, %2;" : "=l"(d) : "l"(a), "l"(b)); return d;
}

// Legendre three-term recurrence on a packed pair of x values.
// P0=1, P1=x, P_{k+1} = c1_k * x * P_k - c2_k * P_{k-1},
// c1_k=(2k+1)/(k+1), c2_k=k/(k+1) (constants folded at compile time).
__device__ __forceinline__ void legendre2(u64 x2, u64 P[NP1]) {
    P[0] = f2_splat(1.0f);
    P[1] = x2;
#pragma unroll
    for (int k = 1; k < NP1 - 1; k++) {
        const float c1 = (float)(2 * k + 1) / (float)(k + 1);
        const float c2 = -(float)k / (float)(k + 1);
        u64 xp = f2_mul(x2, P[k]);
        P[k + 1] = f2_fma(f2_splat(c1), xp, f2_mul(f2_splat(c2), P[k - 1]));
    }
}

__global__ void __launch_bounds__(128, 3)
poly_kernel(const float* __restrict__ x, const float* __restrict__ W,
            const float* __restrict__ bptr, float* __restrict__ out, int N) {
    // Shared: W splatted as {w,w} pairs; 2 consecutive features per 16B slot.
    __shared__ ulonglong2 sW2[NFEAT / 2];  // 8 KB

    for (int e = threadIdx.x; e < NFEAT / 2; e += blockDim.x) {
        float w0 = W[2 * e], w1 = W[2 * e + 1];
        ulonglong2 v;
        v.x = f2_pack(w0, w0);
        v.y = f2_pack(w1, w1);
        sW2[e] = v;
    }
    __syncthreads();

    int npairs = (N + 1) >> 1;
    int p = blockIdx.x * blockDim.x + threadIdx.x;
    if (p >= npairs) return;

    int i0 = 2 * p;
    int i1 = (2 * p + 1 < N) ? (2 * p + 1) : i0;  // degenerate pair for odd tail

    // Load the two points' coordinates and pack lane-wise {ptA, ptB}.
    float a0 = x[3 * i0 + 0], a1 = x[3 * i0 + 1], a2 = x[3 * i0 + 2];
    float b0 = x[3 * i1 + 0], b1 = x[3 * i1 + 1], b2 = x[3 * i1 + 2];
    u64 X0 = f2_pack(a0, b0);
    u64 X1 = f2_pack(a1, b1);
    u64 X2 = f2_pack(a2, b2);

    u64 Px[NP1], Py[NP1], Pz[NP1];
    legendre2(X0, Px);
    legendre2(X1, Py);
    legendre2(X2, Pz);

    u64 r = 0ull;  // bits 0 == {0.f, 0.f}
#pragma unroll
    for (int i = 0; i < NP1; i++) {
        u64 s = 0ull;
#pragma unroll
        for (int j = 0; j < NP1; j++) {
            const ulonglong2* row = sW2 + (i * NP1 + j) * (NP1 / 2);
            u64 t = 0ull;
#pragma unroll
            for (int kk = 0; kk < NP1 / 2; kk++) {
                ulonglong2 w = row[kk];  // LDS.128: {w_{2kk},w_{2kk}, w_{2kk+1},w_{2kk+1}}
                t = f2_fma(w.x, Pz[2 * kk + 0], t);
                t = f2_fma(w.y, Pz[2 * kk + 1], t);
            }
            s = f2_fma(t, Py[j], s);
        }
        r = f2_fma(s, Px[i], r);
    }

    float bb = *bptr;
    float rl, rh;
    f2_unpack(r, rl, rh);
    rl += bb;
    rh += bb;

    if (i1 > i0) {
        // aligned float2 store (i0 even)
        reinterpret_cast<float2*>(out)[p] = make_float2(rl, rh);
    } else {
        out[i0] = rl;
    }
}

extern "C" void kernel_launch(void* const* d_in, const int* in_sizes, int n_in,
                              void* d_out, int out_size) {
    // Identify inputs by size: b has 1 element, x is the largest, W is the rest.
    int ib = -1, ix = -1, iw = -1;
    int max_sz = -1;
    for (int i = 0; i < n_in; i++) {
        if (in_sizes[i] == 1 && ib < 0) ib = i;
        else if (in_sizes[i] > max_sz) { max_sz = in_sizes[i]; ix = i; }
    }
    for (int i = 0; i < n_in; i++) {
        if (i != ib && i != ix) { iw = i; break; }
    }

    const float* x = (const float*)d_in[ix];
    const float* W = (const float*)d_in[iw];
    const float* b = (const float*)d_in[ib];
    float* out = (float*)d_out;

    int N = in_sizes[ix] / 3;
    int npairs = (N + 1) / 2;
    int block = 128;
    int grid = (npairs + block - 1) / block;

    poly_kernel<<<grid, block>>>(x, W, b, out, N);
}

// round 2
// speedup vs baseline: 1.0026x; 1.0026x over previous
#include <cuda_runtime.h>
#include <cstdint>

// MultiVariatePoly: out[n] = sum_{i,j,k} W[i*100+j*10+k] * Px_i * Py_j * Pz_k + b
// DIM=3, ORDER=9. One point per thread; f32x2 packed over (even k, odd k).
// W plain fp32 in shared (4 KB); rows read as ulonglong2 (LDS.128 -> two f32x2 operands).

#define NP1 10
#define NFEAT 1000

typedef unsigned long long u64;

__device__ __forceinline__ u64 f2_pack(float lo, float hi) {
    u64 d; asm("mov.b64 %0, {%1, %2};" : "=l"(d) : "f"(lo), "f"(hi)); return d;
}
__device__ __forceinline__ u64 f2_splat(float s) {
    u64 d; asm("mov.b64 %0, {%1, %1};" : "=l"(d) : "f"(s)); return d;
}
__device__ __forceinline__ void f2_unpack(u64 v, float& lo, float& hi) {
    asm("mov.b64 {%0, %1}, %2;" : "=f"(lo), "=f"(hi) : "l"(v));
}
__device__ __forceinline__ u64 f2_fma(u64 a, u64 b, u64 c) {
    u64 d; asm("fma.rn.f32x2 %0, %1, %2, %3;" : "=l"(d) : "l"(a), "l"(b), "l"(c)); return d;
}
__device__ __forceinline__ u64 f2_mul(u64 a, u64 b) {
    u64 d; asm("mul.rn.f32x2 %0, %1, %2;" : "=l"(d) : "l"(a), "l"(b)); return d;
}

// Scalar Legendre recurrence, constants folded at compile time.
__device__ __forceinline__ void legendre1(float x, float P[NP1]) {
    P[0] = 1.0f;
    P[1] = x;
#pragma unroll
    for (int k = 1; k < NP1 - 1; k++) {
        const float c1 = (float)(2 * k + 1) / (float)(k + 1);
        const float c2 = -(float)k / (float)(k + 1);
        P[k + 1] = c1 * x * P[k] + c2 * P[k - 1];
    }
}

__global__ void __launch_bounds__(128, 5)
poly_kernel(const float* __restrict__ x, const float* __restrict__ W,
            const float* __restrict__ bptr, float* __restrict__ out, int N) {
    // W as plain floats, viewed as ulonglong2 (4 consecutive W values per 16B).
    __shared__ __align__(16) float sW[NFEAT];  // 4 KB

    {
        const float4* Wv = reinterpret_cast<const float4*>(W);
        float4* sWv = reinterpret_cast<float4*>(sW);
        for (int e = threadIdx.x; e < NFEAT / 4; e += blockDim.x) sWv[e] = Wv[e];
    }
    __syncthreads();

    int n = blockIdx.x * blockDim.x + threadIdx.x;
    if (n >= N) return;

    float x0 = x[3 * n + 0], x1 = x[3 * n + 1], x2 = x[3 * n + 2];

    float Px[NP1], Py[NP1], Pz[NP1];
    legendre1(x0, Px);
    legendre1(x1, Py);
    legendre1(x2, Pz);

    // Pz packed as (even,odd) k pairs; Py splatted (each used 10x, keep resident).
    u64 Pzp[NP1 / 2];
#pragma unroll
    for (int kk = 0; kk < NP1 / 2; kk++) Pzp[kk] = f2_pack(Pz[2 * kk], Pz[2 * kk + 1]);
    u64 Pyp[NP1];
#pragma unroll
    for (int j = 0; j < NP1; j++) Pyp[j] = f2_splat(Py[j]);

    const ulonglong2* sWq = reinterpret_cast<const ulonglong2*>(sW);

    u64 r0 = 0ull, r1 = 0ull;  // dual accumulators; bits 0 == {0.f,0.f}
#pragma unroll
    for (int i = 0; i < NP1; i++) {
        const ulonglong2* row = sWq + i * 25;  // i*100 floats = 25 ulonglong2
        u64 s0 = 0ull, s1 = 0ull;
#pragma unroll
        for (int jj = 0; jj < NP1 / 2; jj++) {
            // 20 floats = rows j=2jj and j=2jj+1, as 5 ulonglong2 (each = 2 f32x2 pairs)
            ulonglong2 w0 = row[jj * 5 + 0];
            ulonglong2 w1 = row[jj * 5 + 1];
            ulonglong2 w2 = row[jj * 5 + 2];
            ulonglong2 w3 = row[jj * 5 + 3];
            ulonglong2 w4 = row[jj * 5 + 4];
            // j = 2jj : pairs w0.x w0.y w1.x w1.y w2.x
            u64 t0 = f2_mul(w0.x, Pzp[0]);
            t0 = f2_fma(w0.y, Pzp[1], t0);
            t0 = f2_fma(w1.x, Pzp[2], t0);
            t0 = f2_fma(w1.y, Pzp[3], t0);
            t0 = f2_fma(w2.x, Pzp[4], t0);
            // j = 2jj+1 : pairs w2.y w3.x w3.y w4.x w4.y
            u64 t1 = f2_mul(w2.y, Pzp[0]);
            t1 = f2_fma(w3.x, Pzp[1], t1);
            t1 = f2_fma(w3.y, Pzp[2], t1);
            t1 = f2_fma(w4.x, Pzp[3], t1);
            t1 = f2_fma(w4.y, Pzp[4], t1);
            // independent s chains
            s0 = f2_fma(t0, Pyp[2 * jj + 0], s0);
            s1 = f2_fma(t1, Pyp[2 * jj + 1], s1);
        }
        u64 pxi = f2_splat(Px[i]);
        r0 = f2_fma(s0, pxi, r0);
        r1 = f2_fma(s1, pxi, r1);
    }

    float a0, a1, b0, b1;
    f2_unpack(r0, a0, a1);
    f2_unpack(r1, b0, b1);
    out[n] = (a0 + a1) + (b0 + b1) + *bptr;
}

extern "C" void kernel_launch(void* const* d_in, const int* in_sizes, int n_in,
                              void* d_out, int out_size) {
    // Identify inputs by size: b has 1 element, x is the largest, W is the rest.
    int ib = -1, ix = -1, iw = -1;
    int max_sz = -1;
    for (int i = 0; i < n_in; i++) {
        if (in_sizes[i] == 1 && ib < 0) ib = i;
        else if (in_sizes[i] > max_sz) { max_sz = in_sizes[i]; ix = i; }
    }
    for (int i = 0; i < n_in; i++) {
        if (i != ib && i != ix) { iw = i; break; }
    }

    const float* x = (const float*)d_in[ix];
    const float* W = (const float*)d_in[iw];
    const float* b = (const float*)d_in[ib];
    float* out = (float*)d_out;

    int N = in_sizes[ix] / 3;
    int block = 128;
    int grid = (N + block - 1) / block;

    poly_kernel<<<grid, block>>>(x, W, b, out, N);
}

// round 4
// speedup vs baseline: 1.0322x; 1.0295x over previous
#include <cuda_runtime.h>
#include <cstdint>

// MultiVariatePoly: out[n] = sum_{i,j,k} W[i*100+j*10+k] * Px_i * Py_j * Pz_k + b
// DIM=3, ORDER=9. TWO points per thread sharing each W load.
// f32x2 packed over (even k, odd k); W fp32 in shared, rows read as ulonglong2
// (LDS.128 -> two ready f32x2 operands feeding 4 independent FFMA2 chains).
// (Resubmission of R3 — previous round failed on container infra, no data.)

#define NP1 10
#define NFEAT 1000

typedef unsigned long long u64;

__device__ __forceinline__ u64 f2_pack(float lo, float hi) {
    u64 d; asm("mov.b64 %0, {%1, %2};" : "=l"(d) : "f"(lo), "f"(hi)); return d;
}
__device__ __forceinline__ u64 f2_splat(float s) {
    u64 d; asm("mov.b64 %0, {%1, %1};" : "=l"(d) : "f"(s)); return d;
}
__device__ __forceinline__ void f2_unpack(u64 v, float& lo, float& hi) {
    asm("mov.b64 {%0, %1}, %2;" : "=f"(lo), "=f"(hi) : "l"(v));
}
__device__ __forceinline__ u64 f2_fma(u64 a, u64 b, u64 c) {
    u64 d; asm("fma.rn.f32x2 %0, %1, %2, %3;" : "=l"(d) : "l"(a), "l"(b), "l"(c)); return d;
}
__device__ __forceinline__ u64 f2_mul(u64 a, u64 b) {
    u64 d; asm("mul.rn.f32x2 %0, %1, %2;" : "=l"(d) : "l"(a), "l"(b)); return d;
}

// Scalar Legendre recurrence, constants folded at compile time.
__device__ __forceinline__ void legendre1(float x, float P[NP1]) {
    P[0] = 1.0f;
    P[1] = x;
#pragma unroll
    for (int k = 1; k < NP1 - 1; k++) {
        const float c1 = (float)(2 * k + 1) / (float)(k + 1);
        const float c2 = -(float)k / (float)(k + 1);
        P[k + 1] = c1 * x * P[k] + c2 * P[k - 1];
    }
}

__global__ void __launch_bounds__(128, 4)
poly_kernel(const float* __restrict__ x, const float* __restrict__ W,
            const float* __restrict__ bptr, float* __restrict__ out, int N) {
    __shared__ __align__(16) float sW[NFEAT];  // 4 KB

    {
        const float4* Wv = reinterpret_cast<const float4*>(W);
        float4* sWv = reinterpret_cast<float4*>(sW);
        for (int e = threadIdx.x; e < NFEAT / 4; e += blockDim.x) sWv[e] = Wv[e];
    }
    __syncthreads();

    // Each block covers 256 consecutive points: thread t owns (base+t, base+t+128).
    int base = blockIdx.x * 256;
    int pA = base + threadIdx.x;
    int pB = pA + 128;
    if (pA >= N) return;
    int pBc = (pB < N) ? pB : pA;  // degenerate duplicate for the tail

    float xA0 = x[3 * pA + 0], xA1 = x[3 * pA + 1], xA2 = x[3 * pA + 2];
    float xB0 = x[3 * pBc + 0], xB1 = x[3 * pBc + 1], xB2 = x[3 * pBc + 2];

    float PxA[NP1], PyA[NP1], PzA[NP1];
    float PxB[NP1], PyB[NP1], PzB[NP1];
    legendre1(xA0, PxA); legendre1(xA1, PyA); legendre1(xA2, PzA);
    legendre1(xB0, PxB); legendre1(xB1, PyB); legendre1(xB2, PzB);

    // Pz packed as (even,odd) k pairs — the only resident packed polys.
    u64 PzpA[NP1 / 2], PzpB[NP1 / 2];
#pragma unroll
    for (int kk = 0; kk < NP1 / 2; kk++) {
        PzpA[kk] = f2_pack(PzA[2 * kk], PzA[2 * kk + 1]);
        PzpB[kk] = f2_pack(PzB[2 * kk], PzB[2 * kk + 1]);
    }

    const ulonglong2* sWq = reinterpret_cast<const ulonglong2*>(sW);

    u64 rA0 = 0ull, rA1 = 0ull, rB0 = 0ull, rB1 = 0ull;
#pragma unroll
    for (int i = 0; i < NP1; i++) {
        const ulonglong2* row = sWq + i * 25;  // i*100 floats
        u64 sA0 = 0ull, sA1 = 0ull, sB0 = 0ull, sB1 = 0ull;
#pragma unroll
        for (int jj = 0; jj < NP1 / 2; jj++) {
            // rows j=2jj, j=2jj+1: 20 floats = 5 ulonglong2 (10 f32x2 W pairs)
            ulonglong2 w0 = row[jj * 5 + 0];
            ulonglong2 w1 = row[jj * 5 + 1];
            ulonglong2 w2 = row[jj * 5 + 2];
            ulonglong2 w3 = row[jj * 5 + 3];
            ulonglong2 w4 = row[jj * 5 + 4];

            // Point A/B, j = 2jj (pairs w0.x w0.y w1.x w1.y w2.x)
            // and j = 2jj+1 (pairs w2.y w3.x w3.y w4.x w4.y); 4 indep chains.
            u64 tA0 = f2_mul(w0.x, PzpA[0]);
            u64 tB0 = f2_mul(w0.x, PzpB[0]);
            u64 tA1 = f2_mul(w2.y, PzpA[0]);
            u64 tB1 = f2_mul(w2.y, PzpB[0]);
            tA0 = f2_fma(w0.y, PzpA[1], tA0);
            tB0 = f2_fma(w0.y, PzpB[1], tB0);
            tA1 = f2_fma(w3.x, PzpA[1], tA1);
            tB1 = f2_fma(w3.x, PzpB[1], tB1);
            tA0 = f2_fma(w1.x, PzpA[2], tA0);
            tB0 = f2_fma(w1.x, PzpB[2], tB0);
            tA1 = f2_fma(w3.y, PzpA[2], tA1);
            tB1 = f2_fma(w3.y, PzpB[2], tB1);
            tA0 = f2_fma(w1.y, PzpA[3], tA0);
            tB0 = f2_fma(w1.y, PzpB[3], tB0);
            tA1 = f2_fma(w4.x, PzpA[3], tA1);
            tB1 = f2_fma(w4.x, PzpB[3], tB1);
            tA0 = f2_fma(w2.x, PzpA[4], tA0);
            tB0 = f2_fma(w2.x, PzpB[4], tB0);
            tA1 = f2_fma(w4.y, PzpA[4], tA1);
            tB1 = f2_fma(w4.y, PzpB[4], tB1);

            // fold into s with on-the-fly Py splats (ALU pipe has headroom)
            u64 pyA0 = f2_splat(PyA[2 * jj + 0]);
            u64 pyA1 = f2_splat(PyA[2 * jj + 1]);
            u64 pyB0 = f2_splat(PyB[2 * jj + 0]);
            u64 pyB1 = f2_splat(PyB[2 * jj + 1]);
            sA0 = f2_fma(tA0, pyA0, sA0);
            sA1 = f2_fma(tA1, pyA1, sA1);
            sB0 = f2_fma(tB0, pyB0, sB0);
            sB1 = f2_fma(tB1, pyB1, sB1);
        }
        u64 pxA = f2_splat(PxA[i]);
        u64 pxB = f2_splat(PxB[i]);
        rA0 = f2_fma(sA0, pxA, rA0);
        rA1 = f2_fma(sA1, pxA, rA1);
        rB0 = f2_fma(sB0, pxB, rB0);
        rB1 = f2_fma(sB1, pxB, rB1);
    }

    float bb = *bptr;
    float a0, a1, a2, a3, c0, c1, c2, c3;
    f2_unpack(rA0, a0, a1);
    f2_unpack(rA1, a2, a3);
    f2_unpack(rB0, c0, c1);
    f2_unpack(rB1, c2, c3);

    out[pA] = (a0 + a1) + (a2 + a3) + bb;
    if (pB < N) out[pB] = (c0 + c1) + (c2 + c3) + bb;
}

extern "C" void kernel_launch(void* const* d_in, const int* in_sizes, int n_in,
                              void* d_out, int out_size) {
    // Identify inputs by size: b has 1 element, x is the largest, W is the rest.
    int ib = -1, ix = -1, iw = -1;
    int max_sz = -1;
    for (int i = 0; i < n_in; i++) {
        if (in_sizes[i] == 1 && ib < 0) ib = i;
        else if (in_sizes[i] > max_sz) { max_sz = in_sizes[i]; ix = i; }
    }
    for (int i = 0; i < n_in; i++) {
        if (i != ib && i != ix) { iw = i; break; }
    }

    const float* x = (const float*)d_in[ix];
    const float* W = (const float*)d_in[iw];
    const float* b = (const float*)d_in[ib];
    float* out = (float*)d_out;

    int N = in_sizes[ix] / 3;
    int block = 128;
    int grid = (N + 2 * block - 1) / (2 * block);  // 2 points per thread

    poly_kernel<<<grid, block>>>(x, W, b, out, N);
}